// round 1
// baseline (speedup 1.0000x reference)
#include <cuda_runtime.h>
#include <cuda_bf16.h>
#include <cstdint>

// Problem constants
#define BATCH 4096
#define SEQ   24
#define TT    32
#define VOC   120
#define EMB   128
#define HE    512
#define HD    512
#define START_TOKEN 2

// -------- device scratch (no cudaMalloc allowed) --------
__device__ float g_x[(size_t)TT * BATCH * EMB];        // gathered embeddings [t][b][e]
__device__ float g_encproj[(size_t)BATCH * SEQ * HD];  // enc @ W_enc_attn
__device__ float g_h[(size_t)BATCH * HD];
__device__ float g_c[(size_t)BATCH * HD];
__device__ float g_q[(size_t)BATCH * HD];
__device__ float g_gates[(size_t)BATCH * 4 * HD];
__device__ float g_ctx[(size_t)BATCH * HE];
__device__ float g_ah[(size_t)BATCH * HD];
__device__ float g_logits[(size_t)BATCH * VOC];

__device__ __forceinline__ float tanh_fast(float x) {
    // tanh(x) = 1 - 2/(exp(2x)+1); abs err ~1e-7, handles +-inf saturation
    float e = __expf(2.0f * x);
    return 1.0f - 2.0f / (e + 1.0f);
}
__device__ __forceinline__ float sigmoid_fast(float x) {
    return 1.0f / (1.0f + __expf(-x));
}

// ------------------ generic tiled SGEMM ------------------
// C[M,N] = concat_k(A1[M,K1], A2[M,K2]) * B (+bias1(+bias2)) (optional tanh)
// TRANSB: B given as rows of length K (B1[N,K1], B2[N,K2]) -> C = A * B^T
// else:   B given as [K,N] (B1[K1,N], B2[K2,N])            -> C = A * B
// Requirements: K1 % 16 == 0, (K1+K2) % 16 == 0, all lda/ldb % 4 == 0, M % 64 == 0.
#define GT 64
#define KT 16

template<bool TRANSB, bool DOTANH>
__global__ void sgemm_k(const float* __restrict__ A1, int lda1, int K1,
                        const float* __restrict__ A2, int lda2, int K2,
                        const float* __restrict__ B1, int ldb1,
                        const float* __restrict__ B2, int ldb2,
                        const float* __restrict__ bias1,
                        const float* __restrict__ bias2,
                        float* __restrict__ C, int M, int N)
{
    __shared__ float As[KT][GT];
    __shared__ float Bs[KT][GT];
    const int tid = threadIdx.x;            // 256 threads
    const int bm = blockIdx.y * GT;
    const int bn = blockIdx.x * GT;
    const int K = K1 + K2;
    const int tx = tid & 15, ty = tid >> 4;
    const int m0 = ty * 4, n0 = tx * 4;

    float acc[4][4];
#pragma unroll
    for (int i = 0; i < 4; i++)
#pragma unroll
        for (int j = 0; j < 4; j++) acc[i][j] = 0.0f;

    for (int kt = 0; kt < K; kt += KT) {
        // ---- load A tile (64 rows x 16 k), each thread: float4 across k ----
        {
            int idx = tid * 4;
            int m = idx >> 4;
            int k = idx & 15;              // multiple of 4
            int gm = bm + m;
            int gk = kt + k;
            float4 av = make_float4(0.f, 0.f, 0.f, 0.f);
            if (gm < M) {
                const float* src = (gk < K1)
                    ? (A1 + (size_t)gm * lda1 + gk)
                    : (A2 + (size_t)gm * lda2 + (gk - K1));
                av = *(const float4*)src;
            }
            As[k + 0][m] = av.x; As[k + 1][m] = av.y;
            As[k + 2][m] = av.z; As[k + 3][m] = av.w;
        }
        // ---- load B tile (16 k x 64 n) ----
        if (TRANSB) {
            int idx = tid * 4;
            int n = idx >> 4;
            int k = idx & 15;              // multiple of 4
            int gn = bn + n;
            int gk = kt + k;
            float4 bv = make_float4(0.f, 0.f, 0.f, 0.f);
            if (gn < N) {
                const float* src = (gk < K1)
                    ? (B1 + (size_t)gn * ldb1 + gk)
                    : (B2 + (size_t)gn * ldb2 + (gk - K1));
                bv = *(const float4*)src;
            }
            Bs[k + 0][n] = bv.x; Bs[k + 1][n] = bv.y;
            Bs[k + 2][n] = bv.z; Bs[k + 3][n] = bv.w;
        } else {
            int idx = tid * 4;
            int k = idx >> 6;
            int n = idx & 63;              // multiple of 4
            int gn = bn + n;
            int gk = kt + k;
            float4 bv = make_float4(0.f, 0.f, 0.f, 0.f);
            const float* src = (gk < K1)
                ? (B1 + (size_t)gk * ldb1 + gn)
                : (B2 + (size_t)(gk - K1) * ldb2 + gn);
            if (gn + 3 < N) {
                bv = *(const float4*)src;
            } else {
                if (gn + 0 < N) bv.x = src[0];
                if (gn + 1 < N) bv.y = src[1];
                if (gn + 2 < N) bv.z = src[2];
                if (gn + 3 < N) bv.w = src[3];
            }
            *(float4*)&Bs[k][n] = bv;
        }
        __syncthreads();
#pragma unroll
        for (int k = 0; k < KT; k++) {
            float4 a4 = *(const float4*)&As[k][m0];
            float4 b4 = *(const float4*)&Bs[k][n0];
            float av[4] = { a4.x, a4.y, a4.z, a4.w };
            float bv[4] = { b4.x, b4.y, b4.z, b4.w };
#pragma unroll
            for (int i = 0; i < 4; i++)
#pragma unroll
                for (int j = 0; j < 4; j++)
                    acc[i][j] += av[i] * bv[j];
        }
        __syncthreads();
    }

#pragma unroll
    for (int i = 0; i < 4; i++) {
        int gm = bm + m0 + i;
        if (gm >= M) continue;
#pragma unroll
        for (int j = 0; j < 4; j++) {
            int gn = bn + n0 + j;
            if (gn >= N) continue;
            float v = acc[i][j];
            if (bias1) v += bias1[gn];
            if (bias2) v += bias2[gn];
            if (DOTANH) v = tanh_fast(v);
            C[(size_t)gm * N + gn] = v;
        }
    }
}

// ------------------ small fused kernels ------------------

__global__ void gather_emb_k(const int* __restrict__ tgt,
                             const float* __restrict__ table,
                             float* __restrict__ x)
{
    size_t i = (size_t)blockIdx.x * blockDim.x + threadIdx.x;
    const size_t total = (size_t)TT * BATCH * EMB;
    if (i >= total) return;
    int e = (int)(i % EMB);
    size_t r = i / EMB;
    int b = (int)(r % BATCH);
    int t = (int)(r / BATCH);
    int id = (t == 0) ? START_TOKEN : tgt[(size_t)b * TT + (t - 1)];
    x[i] = table[(size_t)id * EMB + e];
}

__global__ void zero_c_k(float* __restrict__ c)
{
    size_t i = (size_t)blockIdx.x * blockDim.x + threadIdx.x;
    if (i < (size_t)BATCH * HD) c[i] = 0.0f;
}

__global__ void lstm_cell_k(const float* __restrict__ gates,
                            float* __restrict__ h, float* __restrict__ c)
{
    size_t i = (size_t)blockIdx.x * blockDim.x + threadIdx.x;
    if (i >= (size_t)BATCH * HD) return;
    int b = (int)(i / HD);
    int d = (int)(i % HD);
    const float* g = gates + (size_t)b * 4 * HD;
    float ig = sigmoid_fast(g[d]);
    float fg = sigmoid_fast(g[HD + d]);
    float gg = tanh_fast(g[2 * HD + d]);
    float og = sigmoid_fast(g[3 * HD + d]);
    float cn = fg * c[i] + ig * gg;
    c[i] = cn;
    h[i] = og * tanh_fast(cn);
}

// block per batch row; 128 threads
__global__ void attn_k(const float* __restrict__ encproj,
                       const float* __restrict__ enc,
                       const float* __restrict__ q,
                       const float* __restrict__ v_attn,
                       float* __restrict__ attn_out,   // d_out attention region
                       float* __restrict__ ctx,
                       int t)
{
    int b = blockIdx.x;
    int tid = threadIdx.x;
    __shared__ float qsh[HD];
    __shared__ float vsh[HD];
    __shared__ float sc[SEQ];
    __shared__ float aprob[SEQ];

    for (int d = tid; d < HD; d += 128) {
        qsh[d] = q[(size_t)b * HD + d];
        vsh[d] = v_attn[d];
    }
    __syncthreads();

    int w = tid >> 5, lane = tid & 31;
    const float* ep = encproj + (size_t)b * SEQ * HD;
    for (int s = w; s < SEQ; s += 4) {
        float acc = 0.f;
        const float* row = ep + (size_t)s * HD;
        for (int d = lane; d < HD; d += 32)
            acc += tanh_fast(row[d] + qsh[d]) * vsh[d];
#pragma unroll
        for (int o = 16; o; o >>= 1) acc += __shfl_xor_sync(0xffffffffu, acc, o);
        if (lane == 0) sc[s] = acc;
    }
    __syncthreads();

    if (tid < 32) {
        float v = (tid < SEQ) ? sc[tid] : -1e30f;
        float m = v;
#pragma unroll
        for (int o = 16; o; o >>= 1) m = fmaxf(m, __shfl_xor_sync(0xffffffffu, m, o));
        float e = (tid < SEQ) ? __expf(v - m) : 0.f;
        float sum = e;
#pragma unroll
        for (int o = 16; o; o >>= 1) sum += __shfl_xor_sync(0xffffffffu, sum, o);
        float a = e / sum;
        if (tid < SEQ) {
            aprob[tid] = a;
            attn_out[(size_t)b * TT * SEQ + (size_t)t * SEQ + tid] = a;
        }
    }
    __syncthreads();

    const float* erow = enc + (size_t)b * SEQ * HE;
    for (int d = tid; d < HE; d += 128) {
        float acc = 0.f;
#pragma unroll
        for (int s = 0; s < SEQ; s++)
            acc += aprob[s] * erow[(size_t)s * HE + d];
        ctx[(size_t)b * HE + d] = acc;
    }
}

// block per batch row; 128 threads: softmax(logits), p_copy, pointer scatter, final mix
__global__ void out_k(const float* __restrict__ logits,
                      const float* __restrict__ ah,
                      const float* __restrict__ ctx,
                      const float* __restrict__ w_copy,
                      const float* __restrict__ b_copy,
                      const int* __restrict__ input_char_ids,
                      const float* __restrict__ attn,   // d_out attention region
                      float* __restrict__ outputs,
                      int t)
{
    int b = blockIdx.x;
    int tid = threadIdx.x;
    __shared__ float red[128];
    __shared__ float cbuf[VOC];
    __shared__ float psh;

    // p_copy dot product over [ah, ctx] (1024)
    float acc = 0.f;
    const float* ahb = ah + (size_t)b * HD;
    const float* cxb = ctx + (size_t)b * HE;
    for (int k = tid; k < HD; k += 128) acc += ahb[k] * w_copy[k];
    for (int k = tid; k < HE; k += 128) acc += cxb[k] * w_copy[HD + k];
    red[tid] = acc;
    __syncthreads();
    for (int s2 = 64; s2; s2 >>= 1) {
        if (tid < s2) red[tid] += red[tid + s2];
        __syncthreads();
    }
    if (tid == 0) psh = sigmoid_fast(red[0] + b_copy[0]);
    if (tid < VOC) cbuf[tid] = 0.f;
    __syncthreads();

    if (tid < SEQ) {
        int id = input_char_ids[(size_t)b * SEQ + tid];
        float a = attn[(size_t)b * TT * SEQ + (size_t)t * SEQ + tid];
        atomicAdd(&cbuf[id], a);
    }

    float lg = (tid < VOC) ? logits[(size_t)b * VOC + tid] : -1e30f;
    red[tid] = lg;
    __syncthreads();
    for (int s2 = 64; s2; s2 >>= 1) {
        if (tid < s2) red[tid] = fmaxf(red[tid], red[tid + s2]);
        __syncthreads();
    }
    float m = red[0];
    __syncthreads();
    float e = (tid < VOC) ? __expf(lg - m) : 0.f;
    red[tid] = e;
    __syncthreads();
    for (int s2 = 64; s2; s2 >>= 1) {
        if (tid < s2) red[tid] += red[tid + s2];
        __syncthreads();
    }
    float sum = red[0];
    __syncthreads();

    if (tid < VOC) {
        float p = psh;
        float prob = e / sum;
        float o = (1.0f - p) * prob + p * cbuf[tid];
        outputs[(size_t)b * TT * VOC + (size_t)t * VOC + tid] = o;
    }
}

// ------------------ host launcher ------------------

static inline dim3 gemm_grid(int M, int N) {
    return dim3((unsigned)((N + GT - 1) / GT), (unsigned)((M + GT - 1) / GT), 1);
}

extern "C" void kernel_launch(void* const* d_in, const int* in_sizes, int n_in,
                              void* d_out, int out_size)
{
    (void)in_sizes; (void)n_in; (void)out_size;
    const float* enc        = (const float*)d_in[0];   // (B,S,HE)
    const float* enc_final  = (const float*)d_in[1];   // (B,HE)
    const int*   tgt        = (const int*)d_in[2];     // (B,T)
    const int*   input_ids  = (const int*)d_in[3];     // (B,S)
    const float* embed      = (const float*)d_in[4];   // (V,E)
    const float* W_init     = (const float*)d_in[5];   // (HD,HE)
    const float* b_init     = (const float*)d_in[6];
    const float* W_ih       = (const float*)d_in[7];   // (4HD,E)
    const float* W_hh       = (const float*)d_in[8];   // (4HD,HD)
    const float* b_ih       = (const float*)d_in[9];
    const float* b_hh       = (const float*)d_in[10];
    const float* W_enc_attn = (const float*)d_in[11];  // (HE,HD)
    const float* W_dec_attn = (const float*)d_in[12];  // (HD,HD)
    const float* b_attn     = (const float*)d_in[13];
    const float* v_attn     = (const float*)d_in[14];
    const float* W_ap       = (const float*)d_in[15];  // (HD, HD+HE)
    const float* b_ap       = (const float*)d_in[16];
    const float* W_out      = (const float*)d_in[17];  // (V,HD)
    const float* b_out      = (const float*)d_in[18];
    const float* w_copy     = (const float*)d_in[19];  // (HD+HE,)
    const float* b_copy     = (const float*)d_in[20];  // ()

    float* out = (float*)d_out;
    float* outputs   = out;                                 // (B,T,V)
    float* attn_base = out + (size_t)BATCH * TT * VOC;      // (B,T,S)

    float* gx   = nullptr; cudaGetSymbolAddress((void**)&gx,   g_x);
    float* gep  = nullptr; cudaGetSymbolAddress((void**)&gep,  g_encproj);
    float* gh   = nullptr; cudaGetSymbolAddress((void**)&gh,   g_h);
    float* gc   = nullptr; cudaGetSymbolAddress((void**)&gc,   g_c);
    float* gq   = nullptr; cudaGetSymbolAddress((void**)&gq,   g_q);
    float* gg   = nullptr; cudaGetSymbolAddress((void**)&gg,   g_gates);
    float* gctx = nullptr; cudaGetSymbolAddress((void**)&gctx, g_ctx);
    float* gah  = nullptr; cudaGetSymbolAddress((void**)&gah,  g_ah);
    float* glg  = nullptr; cudaGetSymbolAddress((void**)&glg,  g_logits);

    // 1) gather embeddings for all steps (teacher forcing: inputs known)
    {
        size_t total = (size_t)TT * BATCH * EMB;
        gather_emb_k<<<(unsigned)((total + 255) / 256), 256>>>(tgt, embed, gx);
    }
    // 2) h0 = enc_final @ W_init^T + b_init
    sgemm_k<true, false><<<gemm_grid(BATCH, HD), 256>>>(
        enc_final, HE, HE, nullptr, 0, 0,
        W_init, HE, nullptr, 0,
        b_init, nullptr, gh, BATCH, HD);
    // 3) c0 = 0
    zero_c_k<<<(BATCH * HD + 255) / 256, 256>>>(gc);
    // 4) enc_proj = enc @ W_enc_attn   (M = B*S)
    sgemm_k<false, false><<<gemm_grid(BATCH * SEQ, HD), 256>>>(
        enc, HE, HE, nullptr, 0, 0,
        W_enc_attn, HD, nullptr, 0,
        nullptr, nullptr, gep, BATCH * SEQ, HD);

    for (int t = 0; t < TT; t++) {
        // gates = [x_t | h] @ [W_ih | W_hh]^T + b_ih + b_hh
        sgemm_k<true, false><<<gemm_grid(BATCH, 4 * HD), 256>>>(
            gx + (size_t)t * BATCH * EMB, EMB, EMB,
            gh, HD, HD,
            W_ih, EMB, W_hh, HD,
            b_ih, b_hh, gg, BATCH, 4 * HD);
        // LSTM cell
        lstm_cell_k<<<(BATCH * HD + 255) / 256, 256>>>(gg, gh, gc);
        // q = h @ W_dec_attn + b_attn
        sgemm_k<false, false><<<gemm_grid(BATCH, HD), 256>>>(
            gh, HD, HD, nullptr, 0, 0,
            W_dec_attn, HD, nullptr, 0,
            b_attn, nullptr, gq, BATCH, HD);
        // attention: scores, softmax, ctx; writes attentions output
        attn_k<<<BATCH, 128>>>(gep, enc, gq, v_attn, attn_base, gctx, t);
        // ah = tanh([h | ctx] @ W_ap^T + b_ap)
        sgemm_k<true, true><<<gemm_grid(BATCH, HD), 256>>>(
            gh, HD, HD,
            gctx, HE, HE,
            W_ap, HD + HE, W_ap + HD, HD + HE,
            b_ap, nullptr, gah, BATCH, HD);
        // logits = ah @ W_out^T + b_out
        sgemm_k<true, false><<<gemm_grid(BATCH, VOC), 256>>>(
            gah, HD, HD, nullptr, 0, 0,
            W_out, HD, nullptr, 0,
            b_out, nullptr, glg, BATCH, VOC);
        // softmax + pointer-generator mix; writes outputs
        out_k<<<BATCH, 128>>>(glg, gah, gctx, w_copy, b_copy,
                              input_ids, attn_base, outputs, t);
    }
}

// round 3
// speedup vs baseline: 1.9165x; 1.9165x over previous
#include <cuda_runtime.h>
#include <cuda_bf16.h>
#include <cstdint>

#define BATCH 4096
#define SEQ   24
#define TT    32
#define VOC   120
#define EMB   128
#define HE    512
#define HD    512
#define START_TOKEN 2

typedef __nv_bfloat16 bf16;
typedef unsigned int u32;

// ---------------- device scratch (static, no cudaMalloc) ----------------
__device__ __align__(256) bf16 g_xh[(size_t)TT * BATCH * EMB];
__device__ __align__(256) bf16 g_xl[(size_t)TT * BATCH * EMB];
__device__ __align__(256) bf16 g_ench[(size_t)BATCH * SEQ * HE];
__device__ __align__(256) bf16 g_encl[(size_t)BATCH * SEQ * HE];
__device__ __align__(256) bf16 g_efh[(size_t)BATCH * HE];
__device__ __align__(256) bf16 g_efl[(size_t)BATCH * HE];
__device__ __align__(256) float g_encproj[(size_t)BATCH * SEQ * HD];
// weights (bf16 hi/lo)
__device__ __align__(256) bf16 g_wgh[(size_t)4 * HD * (EMB + HD)];
__device__ __align__(256) bf16 g_wgl[(size_t)4 * HD * (EMB + HD)];
__device__ __align__(256) float g_bg[4 * HD];
__device__ __align__(256) bf16 g_wdh[(size_t)HD * HD];
__device__ __align__(256) bf16 g_wdl[(size_t)HD * HD];
__device__ __align__(256) bf16 g_weh[(size_t)HE * HD];
__device__ __align__(256) bf16 g_wel[(size_t)HE * HD];
__device__ __align__(256) bf16 g_waph[(size_t)HD * (HD + HE)];
__device__ __align__(256) bf16 g_wapl[(size_t)HD * (HD + HE)];
__device__ __align__(256) bf16 g_woh[(size_t)VOC * HD];
__device__ __align__(256) bf16 g_wol[(size_t)VOC * HD];
__device__ __align__(256) bf16 g_wih[(size_t)HD * HE];
__device__ __align__(256) bf16 g_wil[(size_t)HD * HE];
// activations
__device__ __align__(256) bf16 g_hh[(size_t)BATCH * HD];
__device__ __align__(256) bf16 g_hl[(size_t)BATCH * HD];
__device__ __align__(256) float g_c[(size_t)BATCH * HD];
__device__ __align__(256) float g_gates[(size_t)BATCH * 4 * HD];
__device__ __align__(256) float g_q[(size_t)BATCH * HD];
__device__ __align__(256) float g_ctx[(size_t)BATCH * HE];
__device__ __align__(256) bf16 g_ctxh[(size_t)BATCH * HE];
__device__ __align__(256) bf16 g_ctxl[(size_t)BATCH * HE];
__device__ __align__(256) float g_ah[(size_t)BATCH * HD];
__device__ __align__(256) bf16 g_ahh[(size_t)BATCH * HD];
__device__ __align__(256) bf16 g_ahl[(size_t)BATCH * HD];
__device__ __align__(256) float g_logits[(size_t)BATCH * VOC];

// ---------------- math helpers ----------------
__device__ __forceinline__ float tanh_fast(float x) {
    float e = __expf(2.0f * x);
    return 1.0f - 2.0f / (e + 1.0f);
}
__device__ __forceinline__ float sigmoid_fast(float x) {
    return 1.0f / (1.0f + __expf(-x));
}
__device__ __forceinline__ void split2(float v, bf16* hi, bf16* lo) {
    bf16 h = __float2bfloat16(v);
    *hi = h;
    *lo = __float2bfloat16(v - __bfloat162float(h));
}

// ---------------- PTX helpers (sm_80-level only; NO tcgen05) ----------------
__device__ __forceinline__ u32 smem_u32(const void* p) {
    u32 a;
    asm("{ .reg .u64 t; cvta.to.shared.u64 t, %1; cvt.u32.u64 %0, t; }"
        : "=r"(a) : "l"(p));
    return a;
}
__device__ __forceinline__ void cp16(u32 d, const void* s, u32 sz) {
    asm volatile("cp.async.cg.shared.global [%0], [%1], 16, %2;"
                 :: "r"(d), "l"(s), "r"(sz) : "memory");
}
__device__ __forceinline__ void cp_commit() {
    asm volatile("cp.async.commit_group;" ::: "memory");
}
template<int N>
__device__ __forceinline__ void cp_wait() {
    asm volatile("cp.async.wait_group %0;" :: "n"(N) : "memory");
}
__device__ __forceinline__ void ldsm_x4(u32* r, u32 a) {
    asm volatile("ldmatrix.sync.aligned.m8n8.x4.shared.b16 {%0,%1,%2,%3}, [%4];"
                 : "=r"(r[0]), "=r"(r[1]), "=r"(r[2]), "=r"(r[3]) : "r"(a));
}
__device__ __forceinline__ void ldsm_x2(u32* r, u32 a) {
    asm volatile("ldmatrix.sync.aligned.m8n8.x2.shared.b16 {%0,%1}, [%2];"
                 : "=r"(r[0]), "=r"(r[1]) : "r"(a));
}
__device__ __forceinline__ void mma_bf16(float* c, const u32* a, const u32* b) {
    asm volatile(
        "mma.sync.aligned.m16n8k16.row.col.f32.bf16.bf16.f32 "
        "{%0,%1,%2,%3}, {%4,%5,%6,%7}, {%8,%9}, {%0,%1,%2,%3};"
        : "+f"(c[0]), "+f"(c[1]), "+f"(c[2]), "+f"(c[3])
        : "r"(a[0]), "r"(a[1]), "r"(a[2]), "r"(a[3]), "r"(b[0]), "r"(b[1]));
}

// ---------------- mma.sync split-bf16 GEMM ----------------
// C[M,N] = concat_K(A1,A2)[M,K] * B[N,K]^T (+bias) (opt tanh) (opt bf16 split-out)
// M % 128 == 0, K % 32 == 0, K1 % 32 == 0, row strides % 8 == 0.
// Grid (ceil(N/128), M/128), 256 threads, dyn smem = GEMM_SMEM.
#define GEMM_SMEM 81920
// per-buffer layout (40960 B): Ah@0  Al@10240  Bh@20480  Bl@30720
// smem row stride = 40 bf16 = 80 B (conflict-free for ldmatrix / cp.async)

template<bool DOTANH, bool SPLITOUT>
__global__ __launch_bounds__(256, 2)
void mma_gemm_k(const bf16* __restrict__ A1h, const bf16* __restrict__ A1l,
                int lda1, int K1,
                const bf16* __restrict__ A2h, const bf16* __restrict__ A2l,
                int lda2,
                const bf16* __restrict__ Bh, const bf16* __restrict__ Bl, int ldb,
                const float* __restrict__ bias,
                float* __restrict__ C, bf16* __restrict__ Ch, bf16* __restrict__ Cl,
                int K, int Nreal)
{
    extern __shared__ char smem[];
    const u32 sb = smem_u32(smem);
    const int tid = threadIdx.x, lane = tid & 31, wid = tid >> 5;
    const int bm = blockIdx.y * 128, bn = blockIdx.x * 128;
    const int wm = (wid >> 1) * 32, wn = (wid & 1) * 64;

    float acc[2][8][4];
#pragma unroll
    for (int m = 0; m < 2; m++)
#pragma unroll
        for (int n = 0; n < 8; n++)
#pragma unroll
            for (int j = 0; j < 4; j++) acc[m][n][j] = 0.0f;

    const int nch = K / 32;

    auto stage = [&](int c) {
        const int kt = c * 32;
        const u32 bufb = sb + (u32)(c & 1) * 40960u;
        const bf16 *Ah_, *Al_;
        int lda, kk;
        if (kt < K1) { Ah_ = A1h; Al_ = A1l; lda = lda1; kk = kt; }
        else         { Ah_ = A2h; Al_ = A2l; lda = lda2; kk = kt - K1; }
#pragma unroll
        for (int p = 0; p < 2; p++) {
            int v = tid + p * 256, row = v >> 2, g = v & 3;
            size_t go = (size_t)(bm + row) * lda + kk + g * 8;
            u32 sa = bufb + row * 80 + g * 16;
            cp16(sa, Ah_ + go, 16);
            cp16(sa + 10240, Al_ + go, 16);
        }
#pragma unroll
        for (int p = 0; p < 2; p++) {
            int v = tid + p * 256, row = v >> 2, g = v & 3;
            int n = bn + row;
            int na = (n < Nreal) ? n : (Nreal - 1);
            u32 sz = (n < Nreal) ? 16u : 0u;
            size_t go = (size_t)na * ldb + kt + g * 8;
            u32 sa = bufb + 20480 + row * 80 + g * 16;
            cp16(sa, Bh + go, sz);
            cp16(sa + 10240, Bl + go, sz);
        }
    };

    stage(0);
    cp_commit();

    for (int c = 0; c < nch; c++) {
        if (c + 1 < nch) {
            stage(c + 1);
            cp_commit();
            cp_wait<1>();
        } else {
            cp_wait<0>();
        }
        __syncthreads();

        const u32 bufb = sb + (u32)(c & 1) * 40960u;
#pragma unroll
        for (int k2 = 0; k2 < 2; k2++) {
            const u32 kb = k2 * 32;
            const u32 aaddr0 = bufb + (wm + (lane & 15)) * 80 + kb + (lane >> 4) * 16;
            const u32 aaddr1 = aaddr0 + 16 * 80;
            u32 ah[2][4], al[2][4];
            ldsm_x4(ah[0], aaddr0);
            ldsm_x4(ah[1], aaddr1);
            ldsm_x4(al[0], aaddr0 + 10240);
            ldsm_x4(al[1], aaddr1 + 10240);
            const u32 bbase = bufb + 20480 +
                (wn + (lane & 7)) * 80 + kb + ((lane >> 3) & 1) * 16;
#pragma unroll
            for (int nt = 0; nt < 8; nt++) {
                u32 ba = bbase + nt * 8 * 80;
                u32 bh[2], bl[2];
                ldsm_x2(bh, ba);
                ldsm_x2(bl, ba + 10240);
#pragma unroll
                for (int m = 0; m < 2; m++) {
                    mma_bf16(acc[m][nt], ah[m], bh);
                    mma_bf16(acc[m][nt], ah[m], bl);
                    mma_bf16(acc[m][nt], al[m], bh);
                }
            }
        }
        __syncthreads();
    }

    // ---- epilogue ----
    auto emit = [&](int r, int n, float v) {
        if (n >= Nreal) return;
        if (bias) v += bias[n];
        if (DOTANH) v = tanh_fast(v);
        size_t o = (size_t)r * Nreal + n;
        if (C) C[o] = v;
        if (SPLITOUT) split2(v, &Ch[o], &Cl[o]);
    };
#pragma unroll
    for (int m = 0; m < 2; m++) {
        int r0 = bm + wm + m * 16 + (lane >> 2);
#pragma unroll
        for (int nt = 0; nt < 8; nt++) {
            int gn = bn + wn + nt * 8 + (lane & 3) * 2;
            emit(r0,     gn,     acc[m][nt][0]);
            emit(r0,     gn + 1, acc[m][nt][1]);
            emit(r0 + 8, gn,     acc[m][nt][2]);
            emit(r0 + 8, gn + 1, acc[m][nt][3]);
        }
    }
}

// ---------------- prep kernels ----------------
__global__ void split_arr_k(const float* __restrict__ src,
                            bf16* __restrict__ h, bf16* __restrict__ l, size_t n)
{
    for (size_t i = (size_t)blockIdx.x * blockDim.x + threadIdx.x; i < n;
         i += (size_t)gridDim.x * blockDim.x)
        split2(src[i], &h[i], &l[i]);
}

__global__ void transpose_split_k(const float* __restrict__ src,  // [K][N]
                                  bf16* __restrict__ h, bf16* __restrict__ l,
                                  int Kd, int Nd)                  // dst [N][K]
{
    size_t n = (size_t)Kd * Nd;
    for (size_t i = (size_t)blockIdx.x * blockDim.x + threadIdx.x; i < n;
         i += (size_t)gridDim.x * blockDim.x) {
        int k = (int)(i / Nd), nn = (int)(i % Nd);
        split2(src[i], &h[(size_t)nn * Kd + k], &l[(size_t)nn * Kd + k]);
    }
}

__global__ void prep_gw_k(const float* __restrict__ Wih, const float* __restrict__ Whh,
                          const float* __restrict__ bih, const float* __restrict__ bhh,
                          bf16* __restrict__ wh, bf16* __restrict__ wl,
                          float* __restrict__ bg)
{
    const size_t n = (size_t)4 * HD * (EMB + HD);
    for (size_t i = (size_t)blockIdx.x * blockDim.x + threadIdx.x; i < n;
         i += (size_t)gridDim.x * blockDim.x) {
        int row = (int)(i / (EMB + HD));
        int k = (int)(i % (EMB + HD));
        float v = (k < EMB) ? Wih[(size_t)row * EMB + k]
                            : Whh[(size_t)row * HD + (k - EMB)];
        split2(v, &wh[i], &wl[i]);
        if (i < (size_t)4 * HD) bg[i] = bih[i] + bhh[i];
    }
}

__global__ void gather_emb_k(const int* __restrict__ tgt,
                             const float* __restrict__ table,
                             bf16* __restrict__ xh, bf16* __restrict__ xl)
{
    const size_t n = (size_t)TT * BATCH * EMB;
    for (size_t i = (size_t)blockIdx.x * blockDim.x + threadIdx.x; i < n;
         i += (size_t)gridDim.x * blockDim.x) {
        int e = (int)(i % EMB);
        size_t r = i / EMB;
        int b = (int)(r % BATCH);
        int t = (int)(r / BATCH);
        int id = (t == 0) ? START_TOKEN : tgt[(size_t)b * TT + (t - 1)];
        split2(table[(size_t)id * EMB + e], &xh[i], &xl[i]);
    }
}

__global__ void zero_c_k(float* __restrict__ c)
{
    size_t i = (size_t)blockIdx.x * blockDim.x + threadIdx.x;
    if (i < (size_t)BATCH * HD) c[i] = 0.0f;
}

__global__ void lstm_cell_k(const float* __restrict__ gates,
                            bf16* __restrict__ hh, bf16* __restrict__ hl,
                            float* __restrict__ c)
{
    size_t i = (size_t)blockIdx.x * blockDim.x + threadIdx.x;
    if (i >= (size_t)BATCH * HD) return;
    int b = (int)(i / HD);
    int d = (int)(i % HD);
    const float* g = gates + (size_t)b * 4 * HD;
    float ig = sigmoid_fast(g[d]);
    float fg = sigmoid_fast(g[HD + d]);
    float gg = tanh_fast(g[2 * HD + d]);
    float og = sigmoid_fast(g[3 * HD + d]);
    float cn = fg * c[i] + ig * gg;
    c[i] = cn;
    float hn = og * tanh_fast(cn);
    split2(hn, &hh[i], &hl[i]);
}

// block per batch row; 128 threads
__global__ void attn_k(const float* __restrict__ encproj,
                       const float* __restrict__ enc,
                       const float* __restrict__ q,
                       const float* __restrict__ v_attn,
                       float* __restrict__ attn_out,
                       float* __restrict__ ctx,
                       bf16* __restrict__ ctxh, bf16* __restrict__ ctxl,
                       int t)
{
    int b = blockIdx.x;
    int tid = threadIdx.x;
    __shared__ float qsh[HD];
    __shared__ float vsh[HD];
    __shared__ float sc[SEQ];
    __shared__ float aprob[SEQ];

    for (int d = tid; d < HD; d += 128) {
        qsh[d] = q[(size_t)b * HD + d];
        vsh[d] = v_attn[d];
    }
    __syncthreads();

    int w = tid >> 5, lane = tid & 31;
    const float* ep = encproj + (size_t)b * SEQ * HD;
    for (int s = w; s < SEQ; s += 4) {
        float acc = 0.f;
        const float* row = ep + (size_t)s * HD;
        for (int d = lane; d < HD; d += 32)
            acc += tanh_fast(row[d] + qsh[d]) * vsh[d];
#pragma unroll
        for (int o = 16; o; o >>= 1) acc += __shfl_xor_sync(0xffffffffu, acc, o);
        if (lane == 0) sc[s] = acc;
    }
    __syncthreads();

    if (tid < 32) {
        float v = (tid < SEQ) ? sc[tid] : -1e30f;
        float m = v;
#pragma unroll
        for (int o = 16; o; o >>= 1) m = fmaxf(m, __shfl_xor_sync(0xffffffffu, m, o));
        float e = (tid < SEQ) ? __expf(v - m) : 0.f;
        float sum = e;
#pragma unroll
        for (int o = 16; o; o >>= 1) sum += __shfl_xor_sync(0xffffffffu, sum, o);
        float a = e / sum;
        if (tid < SEQ) {
            aprob[tid] = a;
            attn_out[(size_t)b * TT * SEQ + (size_t)t * SEQ + tid] = a;
        }
    }
    __syncthreads();

    const float* erow = enc + (size_t)b * SEQ * HE;
    for (int d = tid; d < HE; d += 128) {
        float acc = 0.f;
#pragma unroll
        for (int s = 0; s < SEQ; s++)
            acc += aprob[s] * erow[(size_t)s * HE + d];
        size_t o = (size_t)b * HE + d;
        ctx[o] = acc;
        split2(acc, &ctxh[o], &ctxl[o]);
    }
}

// block per batch row; 128 threads
__global__ void out_k(const float* __restrict__ logits,
                      const float* __restrict__ ah,
                      const float* __restrict__ ctx,
                      const float* __restrict__ w_copy,
                      const float* __restrict__ b_copy,
                      const int* __restrict__ input_char_ids,
                      const float* __restrict__ attn,
                      float* __restrict__ outputs,
                      int t)
{
    int b = blockIdx.x;
    int tid = threadIdx.x;
    __shared__ float red[128];
    __shared__ float cbuf[VOC];
    __shared__ float psh;

    float acc = 0.f;
    const float* ahb = ah + (size_t)b * HD;
    const float* cxb = ctx + (size_t)b * HE;
    for (int k = tid; k < HD; k += 128) acc += ahb[k] * w_copy[k];
    for (int k = tid; k < HE; k += 128) acc += cxb[k] * w_copy[HD + k];
    red[tid] = acc;
    __syncthreads();
    for (int s2 = 64; s2; s2 >>= 1) {
        if (tid < s2) red[tid] += red[tid + s2];
        __syncthreads();
    }
    if (tid == 0) psh = sigmoid_fast(red[0] + b_copy[0]);
    if (tid < VOC) cbuf[tid] = 0.f;
    __syncthreads();

    if (tid < SEQ) {
        int id = input_char_ids[(size_t)b * SEQ + tid];
        float a = attn[(size_t)b * TT * SEQ + (size_t)t * SEQ + tid];
        atomicAdd(&cbuf[id], a);
    }

    float lg = (tid < VOC) ? logits[(size_t)b * VOC + tid] : -1e30f;
    red[tid] = lg;
    __syncthreads();
    for (int s2 = 64; s2; s2 >>= 1) {
        if (tid < s2) red[tid] = fmaxf(red[tid], red[tid + s2]);
        __syncthreads();
    }
    float m = red[0];
    __syncthreads();
    float e = (tid < VOC) ? __expf(lg - m) : 0.f;
    red[tid] = e;
    __syncthreads();
    for (int s2 = 64; s2; s2 >>= 1) {
        if (tid < s2) red[tid] += red[tid + s2];
        __syncthreads();
    }
    float sum = red[0];
    __syncthreads();

    if (tid < VOC) {
        float p = psh;
        float prob = e / sum;
        float o = (1.0f - p) * prob + p * cbuf[tid];
        outputs[(size_t)b * TT * VOC + (size_t)t * VOC + tid] = o;
    }
}

// ---------------- host ----------------
#define SYM(p, s) cudaGetSymbolAddress((void**)&(p), s)

extern "C" void kernel_launch(void* const* d_in, const int* in_sizes, int n_in,
                              void* d_out, int out_size)
{
    (void)in_sizes; (void)n_in; (void)out_size;
    const float* enc        = (const float*)d_in[0];
    const float* enc_final  = (const float*)d_in[1];
    const int*   tgt        = (const int*)d_in[2];
    const int*   input_ids  = (const int*)d_in[3];
    const float* embed      = (const float*)d_in[4];
    const float* W_init     = (const float*)d_in[5];
    const float* b_init     = (const float*)d_in[6];
    const float* W_ih       = (const float*)d_in[7];
    const float* W_hh       = (const float*)d_in[8];
    const float* b_ih       = (const float*)d_in[9];
    const float* b_hh       = (const float*)d_in[10];
    const float* W_enc_attn = (const float*)d_in[11];
    const float* W_dec_attn = (const float*)d_in[12];
    const float* b_attn     = (const float*)d_in[13];
    const float* v_attn     = (const float*)d_in[14];
    const float* W_ap       = (const float*)d_in[15];
    const float* b_ap       = (const float*)d_in[16];
    const float* W_out      = (const float*)d_in[17];
    const float* b_out      = (const float*)d_in[18];
    const float* w_copy     = (const float*)d_in[19];
    const float* b_copy     = (const float*)d_in[20];

    float* out = (float*)d_out;
    float* outputs   = out;
    float* attn_base = out + (size_t)BATCH * TT * VOC;

    bf16 *xh, *xl, *ench, *encl, *efh, *efl;
    bf16 *wgh, *wgl, *wdh, *wdl, *weh, *wel, *waph, *wapl, *woh, *wol, *wih, *wil;
    bf16 *hh, *hl, *ctxh, *ctxl, *ahh, *ahl;
    float *encproj, *bg, *cst, *gates, *q, *ctx, *ah, *logits;
    SYM(xh, g_xh);   SYM(xl, g_xl);
    SYM(ench, g_ench); SYM(encl, g_encl);
    SYM(efh, g_efh); SYM(efl, g_efl);
    SYM(encproj, g_encproj);
    SYM(wgh, g_wgh); SYM(wgl, g_wgl); SYM(bg, g_bg);
    SYM(wdh, g_wdh); SYM(wdl, g_wdl);
    SYM(weh, g_weh); SYM(wel, g_wel);
    SYM(waph, g_waph); SYM(wapl, g_wapl);
    SYM(woh, g_woh); SYM(wol, g_wol);
    SYM(wih, g_wih); SYM(wil, g_wil);
    SYM(hh, g_hh);   SYM(hl, g_hl);
    SYM(cst, g_c);   SYM(gates, g_gates);
    SYM(q, g_q);     SYM(ctx, g_ctx);
    SYM(ctxh, g_ctxh); SYM(ctxl, g_ctxl);
    SYM(ah, g_ah);   SYM(ahh, g_ahh); SYM(ahl, g_ahl);
    SYM(logits, g_logits);

    cudaFuncSetAttribute(mma_gemm_k<false, false>,
                         cudaFuncAttributeMaxDynamicSharedMemorySize, GEMM_SMEM);
    cudaFuncSetAttribute(mma_gemm_k<false, true>,
                         cudaFuncAttributeMaxDynamicSharedMemorySize, GEMM_SMEM);
    cudaFuncSetAttribute(mma_gemm_k<true, true>,
                         cudaFuncAttributeMaxDynamicSharedMemorySize, GEMM_SMEM);

    const int PB = 4096;

    // ---- prep ----
    split_arr_k<<<PB, 256>>>(enc, ench, encl, (size_t)BATCH * SEQ * HE);
    split_arr_k<<<PB, 256>>>(enc_final, efh, efl, (size_t)BATCH * HE);
    gather_emb_k<<<PB, 256>>>(tgt, embed, xh, xl);
    prep_gw_k<<<PB, 256>>>(W_ih, W_hh, b_ih, b_hh, wgh, wgl, bg);
    transpose_split_k<<<1024, 256>>>(W_dec_attn, wdh, wdl, HD, HD);
    transpose_split_k<<<1024, 256>>>(W_enc_attn, weh, wel, HE, HD);
    split_arr_k<<<1024, 256>>>(W_ap, waph, wapl, (size_t)HD * (HD + HE));
    split_arr_k<<<256, 256>>>(W_out, woh, wol, (size_t)VOC * HD);
    split_arr_k<<<1024, 256>>>(W_init, wih, wil, (size_t)HD * HE);
    zero_c_k<<<(BATCH * HD + 255) / 256, 256>>>(cst);

    // h0 = enc_final @ W_init^T + b_init  -> split into (hh, hl)
    mma_gemm_k<false, true><<<dim3(4, 32), 256, GEMM_SMEM>>>(
        efh, efl, HE, HE, nullptr, nullptr, 0,
        wih, wil, HE, b_init,
        nullptr, hh, hl, HE, HD);
    // enc_proj = enc @ W_enc_attn  (B = transposed W_enc_attn)
    mma_gemm_k<false, false><<<dim3(4, 768), 256, GEMM_SMEM>>>(
        ench, encl, HE, HE, nullptr, nullptr, 0,
        weh, wel, HE, nullptr,
        encproj, nullptr, nullptr, HE, HD);

    for (int t = 0; t < TT; t++) {
        // gates = [x_t | h] @ Wg^T + (b_ih + b_hh)
        mma_gemm_k<false, false><<<dim3(16, 32), 256, GEMM_SMEM>>>(
            xh + (size_t)t * BATCH * EMB, xl + (size_t)t * BATCH * EMB, EMB, EMB,
            hh, hl, HD,
            wgh, wgl, EMB + HD, bg,
            gates, nullptr, nullptr, EMB + HD, 4 * HD);
        lstm_cell_k<<<(BATCH * HD + 255) / 256, 256>>>(gates, hh, hl, cst);
        // q = h @ W_dec_attn + b_attn
        mma_gemm_k<false, false><<<dim3(4, 32), 256, GEMM_SMEM>>>(
            hh, hl, HD, HD, nullptr, nullptr, 0,
            wdh, wdl, HD, b_attn,
            q, nullptr, nullptr, HD, HD);
        attn_k<<<BATCH, 128>>>(encproj, enc, q, v_attn, attn_base,
                               ctx, ctxh, ctxl, t);
        // ah = tanh([h | ctx] @ W_ap^T + b_ap), also split
        mma_gemm_k<true, true><<<dim3(4, 32), 256, GEMM_SMEM>>>(
            hh, hl, HD, HD,
            ctxh, ctxl, HE,
            waph, wapl, HD + HE, b_ap,
            ah, ahh, ahl, HD + HE, HD);
        // logits = ah @ W_out^T + b_out
        mma_gemm_k<false, false><<<dim3(1, 32), 256, GEMM_SMEM>>>(
            ahh, ahl, HD, HD, nullptr, nullptr, 0,
            woh, wol, HD, b_out,
            logits, nullptr, nullptr, HD, VOC);
        out_k<<<BATCH, 128>>>(logits, ah, ctx, w_copy, b_copy,
                              input_ids, attn_base, outputs, t);
    }
}

// round 4
// speedup vs baseline: 2.1410x; 1.1171x over previous
#include <cuda_runtime.h>
#include <cuda_bf16.h>
#include <cstdint>

#define BATCH 4096
#define SEQ   24
#define TT    32
#define VOC   120
#define EMB   128
#define HE    512
#define HD    512
#define START_TOKEN 2

typedef __nv_bfloat16 bf16;
typedef unsigned int u32;

// ---------------- device scratch ----------------
__device__ __align__(256) bf16 g_ench[(size_t)BATCH * SEQ * HE];
__device__ __align__(256) bf16 g_encl[(size_t)BATCH * SEQ * HE];
__device__ __align__(256) bf16 g_efh[(size_t)BATCH * HE];
__device__ __align__(256) bf16 g_efl[(size_t)BATCH * HE];
__device__ __align__(256) float g_encproj[(size_t)BATCH * SEQ * HD];
__device__ __align__(256) float g_embproj[(size_t)VOC * 4 * HD];
// weights (bf16 hi/lo)
__device__ __align__(256) bf16 g_wgh[(size_t)4 * HD * HD];   // W_hh split
__device__ __align__(256) bf16 g_wgl[(size_t)4 * HD * HD];
__device__ __align__(256) bf16 g_wdh[(size_t)HD * HD];
__device__ __align__(256) bf16 g_wdl[(size_t)HD * HD];
__device__ __align__(256) bf16 g_weh[(size_t)HE * HD];
__device__ __align__(256) bf16 g_wel[(size_t)HE * HD];
__device__ __align__(256) bf16 g_waph[(size_t)HD * (HD + HE)];
__device__ __align__(256) bf16 g_wapl[(size_t)HD * (HD + HE)];
__device__ __align__(256) bf16 g_woch[(size_t)121 * HD];     // [W_out; w_copy_ah]
__device__ __align__(256) bf16 g_wocl[(size_t)121 * HD];
__device__ __align__(256) float g_boc[121];
__device__ __align__(256) bf16 g_wih[(size_t)HD * HE];
__device__ __align__(256) bf16 g_wil[(size_t)HD * HE];
// activations
__device__ __align__(256) bf16 g_hh[(size_t)BATCH * HD];
__device__ __align__(256) bf16 g_hl[(size_t)BATCH * HD];
__device__ __align__(256) float g_c[(size_t)BATCH * HD];
__device__ __align__(256) float g_gates[(size_t)BATCH * 4 * HD];
__device__ __align__(256) float g_q[(size_t)BATCH * HD];
__device__ __align__(256) bf16 g_ctxh[(size_t)BATCH * HE];
__device__ __align__(256) bf16 g_ctxl[(size_t)BATCH * HE];
__device__ __align__(256) bf16 g_ahh_all[(size_t)TT * BATCH * HD];
__device__ __align__(256) bf16 g_ahl_all[(size_t)TT * BATCH * HD];
__device__ __align__(256) float g_logits_all[(size_t)TT * BATCH * 121];
__device__ __align__(256) float g_ctxdot[(size_t)TT * BATCH];

// ---------------- math helpers ----------------
__device__ __forceinline__ float tanh_fast(float x) {
    float e = __expf(2.0f * x);
    return 1.0f - 2.0f / (e + 1.0f);
}
__device__ __forceinline__ float sigmoid_fast(float x) {
    return 1.0f / (1.0f + __expf(-x));
}
__device__ __forceinline__ void split2(float v, bf16* hi, bf16* lo) {
    bf16 h = __float2bfloat16(v);
    *hi = h;
    *lo = __float2bfloat16(v - __bfloat162float(h));
}

// ---------------- PTX helpers (sm_80-level) ----------------
__device__ __forceinline__ u32 smem_u32(const void* p) {
    u32 a;
    asm("{ .reg .u64 t; cvta.to.shared.u64 t, %1; cvt.u32.u64 %0, t; }"
        : "=r"(a) : "l"(p));
    return a;
}
__device__ __forceinline__ void cp16(u32 d, const void* s, u32 sz) {
    asm volatile("cp.async.cg.shared.global [%0], [%1], 16, %2;"
                 :: "r"(d), "l"(s), "r"(sz) : "memory");
}
__device__ __forceinline__ void cp_commit() {
    asm volatile("cp.async.commit_group;" ::: "memory");
}
template<int N>
__device__ __forceinline__ void cp_wait() {
    asm volatile("cp.async.wait_group %0;" :: "n"(N) : "memory");
}
__device__ __forceinline__ void ldsm_x4(u32* r, u32 a) {
    asm volatile("ldmatrix.sync.aligned.m8n8.x4.shared.b16 {%0,%1,%2,%3}, [%4];"
                 : "=r"(r[0]), "=r"(r[1]), "=r"(r[2]), "=r"(r[3]) : "r"(a));
}
__device__ __forceinline__ void mma_bf16(float* c, const u32* a, const u32* b) {
    asm volatile(
        "mma.sync.aligned.m16n8k16.row.col.f32.bf16.bf16.f32 "
        "{%0,%1,%2,%3}, {%4,%5,%6,%7}, {%8,%9}, {%0,%1,%2,%3};"
        : "+f"(c[0]), "+f"(c[1]), "+f"(c[2]), "+f"(c[3])
        : "r"(a[0]), "r"(a[1]), "r"(a[2]), "r"(a[3]), "r"(b[0]), "r"(b[1]));
}

// ---------------- mma.sync split-bf16 GEMM ----------------
// C[M,BNtile...] = concat_K(A1,A2)[M,K] * B[N,K]^T (+bias) (opt tanh/splitout)
// M % 128 == 0, K % 32 == 0, K1 % 32 == 0, row strides % 8 == 0.
// Grid (ceil(N/BN), M/128), 256 threads.
// per-buffer layout: Ah@0 Al@10240 Bh@20480 Bl@20480+BN*80; row stride 80 B.

template<int BN, bool DOTANH, bool SPLITOUT>
__global__ __launch_bounds__(256, 2)
void mma_gemm_k(const bf16* __restrict__ A1h, const bf16* __restrict__ A1l,
                int lda1, int K1,
                const bf16* __restrict__ A2h, const bf16* __restrict__ A2l,
                int lda2,
                const bf16* __restrict__ Bh, const bf16* __restrict__ Bl, int ldb,
                const float* __restrict__ bias,
                float* __restrict__ C, bf16* __restrict__ Ch, bf16* __restrict__ Cl,
                int K, int Nreal)
{
    constexpr int BUFB = 20480 + BN * 160;   // bytes per stage buffer
    constexpr int BLO  = BN * 80;            // B lo offset from B hi
    constexpr int NTN  = BN / 16;            // n-tiles (8 cols) per warp

    extern __shared__ char smem[];
    const u32 sb = smem_u32(smem);
    const int tid = threadIdx.x, lane = tid & 31, wid = tid >> 5;
    const int bm = blockIdx.y * 128, bn = blockIdx.x * BN;
    const int wm = (wid >> 1) * 32, wn = (wid & 1) * (BN / 2);

    float acc[2][NTN][4];
#pragma unroll
    for (int m = 0; m < 2; m++)
#pragma unroll
        for (int n = 0; n < NTN; n++)
#pragma unroll
            for (int j = 0; j < 4; j++) acc[m][n][j] = 0.0f;

    const int nch = K / 32;

    auto stage = [&](int c) {
        const int kt = c * 32;
        const u32 bufb = sb + (u32)(c & 1) * BUFB;
        const bf16 *Ah_, *Al_;
        int lda, kk;
        if (kt < K1) { Ah_ = A1h; Al_ = A1l; lda = lda1; kk = kt; }
        else         { Ah_ = A2h; Al_ = A2l; lda = lda2; kk = kt - K1; }
#pragma unroll
        for (int p = 0; p < 2; p++) {
            int v = tid + p * 256, row = v >> 2, g = v & 3;
            size_t go = (size_t)(bm + row) * lda + kk + g * 8;
            u32 sa = bufb + row * 80 + g * 16;
            cp16(sa, Ah_ + go, 16);
            cp16(sa + 10240, Al_ + go, 16);
        }
#pragma unroll
        for (int p = 0; p < BN / 64; p++) {
            int v = tid + p * 256, row = v >> 2, g = v & 3;
            int n = bn + row;
            int na = (n < Nreal) ? n : (Nreal - 1);
            u32 sz = (n < Nreal) ? 16u : 0u;
            size_t go = (size_t)na * ldb + kt + g * 8;
            u32 sa = bufb + 20480 + row * 80 + g * 16;
            cp16(sa, Bh + go, sz);
            cp16(sa + BLO, Bl + go, sz);
        }
    };

    stage(0);
    cp_commit();

    for (int c = 0; c < nch; c++) {
        if (c + 1 < nch) {
            stage(c + 1);
            cp_commit();
            cp_wait<1>();
        } else {
            cp_wait<0>();
        }
        __syncthreads();

        const u32 bufb = sb + (u32)(c & 1) * BUFB;
#pragma unroll
        for (int k2 = 0; k2 < 2; k2++) {
            const u32 kb = k2 * 32;
            const u32 aaddr0 = bufb + (wm + (lane & 15)) * 80 + kb + (lane >> 4) * 16;
            const u32 aaddr1 = aaddr0 + 16 * 80;
            u32 ah[2][4], al[2][4];
            ldsm_x4(ah[0], aaddr0);
            ldsm_x4(ah[1], aaddr1);
            ldsm_x4(al[0], aaddr0 + 10240);
            ldsm_x4(al[1], aaddr1 + 10240);
            // B: x4 loads fetch two adjacent 8-col fragments
            const u32 bb0 = bufb + 20480 +
                (wn + (lane & 7) + ((lane >> 4) & 1) * 8) * 80 +
                kb + ((lane >> 3) & 1) * 16;
#pragma unroll
            for (int nt2 = 0; nt2 < NTN / 2; nt2++) {
                u32 ba = bb0 + nt2 * 16 * 80;
                u32 bh4[4], bl4[4];
                ldsm_x4(bh4, ba);
                ldsm_x4(bl4, ba + BLO);
#pragma unroll
                for (int half = 0; half < 2; half++) {
                    int nt = nt2 * 2 + half;
                    const u32* bh = bh4 + half * 2;
                    const u32* bl = bl4 + half * 2;
#pragma unroll
                    for (int m = 0; m < 2; m++) {
                        mma_bf16(acc[m][nt], ah[m], bh);
                        mma_bf16(acc[m][nt], ah[m], bl);
                        mma_bf16(acc[m][nt], al[m], bh);
                    }
                }
            }
        }
        __syncthreads();
    }

    // ---- epilogue ----
    auto emit = [&](int r, int n, float v) {
        if (n >= Nreal) return;
        if (bias) v += bias[n];
        if (DOTANH) v = tanh_fast(v);
        size_t o = (size_t)r * Nreal + n;
        if (C) C[o] = v;
        if (SPLITOUT) split2(v, &Ch[o], &Cl[o]);
    };
#pragma unroll
    for (int m = 0; m < 2; m++) {
        int r0 = bm + wm + m * 16 + (lane >> 2);
#pragma unroll
        for (int nt = 0; nt < NTN; nt++) {
            int gn = bn + wn + nt * 8 + (lane & 3) * 2;
            emit(r0,     gn,     acc[m][nt][0]);
            emit(r0,     gn + 1, acc[m][nt][1]);
            emit(r0 + 8, gn,     acc[m][nt][2]);
            emit(r0 + 8, gn + 1, acc[m][nt][3]);
        }
    }
}

// ---------------- prep kernels ----------------
__global__ void split_arr_k(const float* __restrict__ src,
                            bf16* __restrict__ h, bf16* __restrict__ l, size_t n)
{
    for (size_t i = (size_t)blockIdx.x * blockDim.x + threadIdx.x; i < n;
         i += (size_t)gridDim.x * blockDim.x)
        split2(src[i], &h[i], &l[i]);
}

__global__ void transpose_split_k(const float* __restrict__ src,  // [K][N]
                                  bf16* __restrict__ h, bf16* __restrict__ l,
                                  int Kd, int Nd)                  // dst [N][K]
{
    size_t n = (size_t)Kd * Nd;
    for (size_t i = (size_t)blockIdx.x * blockDim.x + threadIdx.x; i < n;
         i += (size_t)gridDim.x * blockDim.x) {
        int k = (int)(i / Nd), nn = (int)(i % Nd);
        split2(src[i], &h[(size_t)nn * Kd + k], &l[(size_t)nn * Kd + k]);
    }
}

// emb_proj[v][j] = sum_k embed[v][k] * W_ih[j][k] + b_ih[j] + b_hh[j]
__global__ void embproj_k(const float* __restrict__ embed,
                          const float* __restrict__ W_ih,
                          const float* __restrict__ b_ih,
                          const float* __restrict__ b_hh,
                          float* __restrict__ ep)
{
    int v = blockIdx.y;
    int j = blockIdx.x * 128 + threadIdx.x;
    __shared__ float em[EMB];
    if (threadIdx.x < EMB) em[threadIdx.x] = embed[(size_t)v * EMB + threadIdx.x];
    __syncthreads();
    float acc = b_ih[j] + b_hh[j];
    const float* w = W_ih + (size_t)j * EMB;
#pragma unroll 8
    for (int k = 0; k < EMB; k++) acc += em[k] * w[k];
    ep[(size_t)v * 4 * HD + j] = acc;
}

// output weight: rows 0..119 = W_out, row 120 = w_copy[0:512]; bias likewise
__global__ void prep_outw_k(const float* __restrict__ W_out,
                            const float* __restrict__ b_out,
                            const float* __restrict__ w_copy,
                            const float* __restrict__ b_copy,
                            bf16* __restrict__ wh, bf16* __restrict__ wl,
                            float* __restrict__ bo)
{
    size_t n = (size_t)121 * HD;
    for (size_t i = (size_t)blockIdx.x * blockDim.x + threadIdx.x; i < n;
         i += (size_t)gridDim.x * blockDim.x) {
        int row = (int)(i / HD), k = (int)(i % HD);
        float v = (row < VOC) ? W_out[(size_t)row * HD + k] : w_copy[k];
        split2(v, &wh[i], &wl[i]);
        if (i < 121) bo[i] = (i < VOC) ? b_out[i] : b_copy[0];
    }
}

__global__ void zero_c_k(float* __restrict__ c)
{
    size_t i = (size_t)blockIdx.x * blockDim.x + threadIdx.x;
    if (i < (size_t)BATCH * HD) c[i] = 0.0f;
}

__global__ void lstm_cell_k(const float* __restrict__ gates,  // h@W_hh^T part
                            const float* __restrict__ ep,     // emb_proj
                            const int* __restrict__ tgt,
                            bf16* __restrict__ hh, bf16* __restrict__ hl,
                            float* __restrict__ c, int t)
{
    size_t i = (size_t)blockIdx.x * blockDim.x + threadIdx.x;
    if (i >= (size_t)BATCH * HD) return;
    int b = (int)(i / HD);
    int d = (int)(i % HD);
    int tok = (t == 0) ? START_TOKEN : tgt[(size_t)b * TT + (t - 1)];
    const float* g = gates + (size_t)b * 4 * HD;
    const float* e = ep + (size_t)tok * 4 * HD;
    float ig = sigmoid_fast(g[d] + e[d]);
    float fg = sigmoid_fast(g[HD + d] + e[HD + d]);
    float gg = tanh_fast(g[2 * HD + d] + e[2 * HD + d]);
    float og = sigmoid_fast(g[3 * HD + d] + e[3 * HD + d]);
    float cn = fg * c[i] + ig * gg;
    c[i] = cn;
    float hn = og * tanh_fast(cn);
    split2(hn, &hh[i], &hl[i]);
}

// block per batch row; 128 threads
__global__ void attn_k(const float* __restrict__ encproj,
                       const float* __restrict__ enc,
                       const float* __restrict__ q,
                       const float* __restrict__ v_attn,
                       const float* __restrict__ w_copy,   // use [512:1024]
                       float* __restrict__ attn_out,
                       bf16* __restrict__ ctxh, bf16* __restrict__ ctxl,
                       float* __restrict__ ctxdot,
                       int t)
{
    int b = blockIdx.x;
    int tid = threadIdx.x;
    __shared__ float qsh[HD];
    __shared__ float vsh[HD];
    __shared__ float wsh[HE];
    __shared__ float sc[SEQ];
    __shared__ float aprob[SEQ];
    __shared__ float red[128];

    for (int d = tid; d < HD; d += 128) {
        qsh[d] = q[(size_t)b * HD + d];
        vsh[d] = v_attn[d];
        wsh[d] = w_copy[HD + d];
    }
    __syncthreads();

    int w = tid >> 5, lane = tid & 31;
    const float* ep = encproj + (size_t)b * SEQ * HD;
    for (int s = w; s < SEQ; s += 4) {
        float acc = 0.f;
        const float* row = ep + (size_t)s * HD;
        for (int d = lane; d < HD; d += 32)
            acc += tanh_fast(row[d] + qsh[d]) * vsh[d];
#pragma unroll
        for (int o = 16; o; o >>= 1) acc += __shfl_xor_sync(0xffffffffu, acc, o);
        if (lane == 0) sc[s] = acc;
    }
    __syncthreads();

    if (tid < 32) {
        float v = (tid < SEQ) ? sc[tid] : -1e30f;
        float m = v;
#pragma unroll
        for (int o = 16; o; o >>= 1) m = fmaxf(m, __shfl_xor_sync(0xffffffffu, m, o));
        float e = (tid < SEQ) ? __expf(v - m) : 0.f;
        float sum = e;
#pragma unroll
        for (int o = 16; o; o >>= 1) sum += __shfl_xor_sync(0xffffffffu, sum, o);
        float a = e / sum;
        if (tid < SEQ) {
            aprob[tid] = a;
            attn_out[(size_t)b * TT * SEQ + (size_t)t * SEQ + tid] = a;
        }
    }
    __syncthreads();

    const float* erow = enc + (size_t)b * SEQ * HE;
    float part = 0.f;
    for (int d = tid; d < HE; d += 128) {
        float acc = 0.f;
#pragma unroll
        for (int s = 0; s < SEQ; s++)
            acc += aprob[s] * erow[(size_t)s * HE + d];
        size_t o = (size_t)b * HE + d;
        split2(acc, &ctxh[o], &ctxl[o]);
        part += acc * wsh[d];
    }
    red[tid] = part;
    __syncthreads();
    for (int s2 = 64; s2; s2 >>= 1) {
        if (tid < s2) red[tid] += red[tid + s2];
        __syncthreads();
    }
    if (tid == 0) ctxdot[(size_t)t * BATCH + b] = red[0];
}

// one block per (t,b): softmax + pointer-generator mix
__global__ void out2_k(const float* __restrict__ logits_all,  // [T*B][121]
                       const float* __restrict__ ctxdot,      // [T*B]
                       const int* __restrict__ input_char_ids,
                       const float* __restrict__ attn_base,
                       float* __restrict__ outputs)
{
    int row = blockIdx.x;          // t*B + b
    int t = row >> 12;             // / 4096
    int b = row & 4095;
    int tid = threadIdx.x;
    __shared__ float red[128];
    __shared__ float cbuf[VOC];
    __shared__ float psh;

    const float* lrow = logits_all + (size_t)row * 121;
    if (tid == 0) psh = sigmoid_fast(lrow[120] + ctxdot[row]);
    if (tid < VOC) cbuf[tid] = 0.f;
    __syncthreads();

    if (tid < SEQ) {
        int id = input_char_ids[(size_t)b * SEQ + tid];
        float a = attn_base[(size_t)b * TT * SEQ + (size_t)t * SEQ + tid];
        atomicAdd(&cbuf[id], a);
    }

    float lg = (tid < VOC) ? lrow[tid] : -1e30f;
    red[tid] = lg;
    __syncthreads();
    for (int s2 = 64; s2; s2 >>= 1) {
        if (tid < s2) red[tid] = fmaxf(red[tid], red[tid + s2]);
        __syncthreads();
    }
    float m = red[0];
    __syncthreads();
    float e = (tid < VOC) ? __expf(lg - m) : 0.f;
    red[tid] = e;
    __syncthreads();
    for (int s2 = 64; s2; s2 >>= 1) {
        if (tid < s2) red[tid] += red[tid + s2];
        __syncthreads();
    }
    float sum = red[0];
    __syncthreads();

    if (tid < VOC) {
        float p = psh;
        outputs[(size_t)b * TT * VOC + (size_t)t * VOC + tid] =
            (1.0f - p) * (e / sum) + p * cbuf[tid];
    }
}

// ---------------- host ----------------
#define SYM(p, s) cudaGetSymbolAddress((void**)&(p), s)
#define SM128 81920
#define SM64  61440

extern "C" void kernel_launch(void* const* d_in, const int* in_sizes, int n_in,
                              void* d_out, int out_size)
{
    (void)in_sizes; (void)n_in; (void)out_size;
    const float* enc        = (const float*)d_in[0];
    const float* enc_final  = (const float*)d_in[1];
    const int*   tgt        = (const int*)d_in[2];
    const int*   input_ids  = (const int*)d_in[3];
    const float* embed      = (const float*)d_in[4];
    const float* W_init     = (const float*)d_in[5];
    const float* b_init     = (const float*)d_in[6];
    const float* W_ih       = (const float*)d_in[7];
    const float* W_hh       = (const float*)d_in[8];
    const float* b_ih       = (const float*)d_in[9];
    const float* b_hh       = (const float*)d_in[10];
    const float* W_enc_attn = (const float*)d_in[11];
    const float* W_dec_attn = (const float*)d_in[12];
    const float* b_attn     = (const float*)d_in[13];
    const float* v_attn     = (const float*)d_in[14];
    const float* W_ap       = (const float*)d_in[15];
    const float* b_ap       = (const float*)d_in[16];
    const float* W_out      = (const float*)d_in[17];
    const float* b_out      = (const float*)d_in[18];
    const float* w_copy     = (const float*)d_in[19];
    const float* b_copy     = (const float*)d_in[20];

    float* out = (float*)d_out;
    float* outputs   = out;
    float* attn_base = out + (size_t)BATCH * TT * VOC;

    bf16 *ench, *encl, *efh, *efl;
    bf16 *wgh, *wgl, *wdh, *wdl, *weh, *wel, *waph, *wapl, *woch, *wocl, *wih, *wil;
    bf16 *hh, *hl, *ctxh, *ctxl, *ahh, *ahl;
    float *encproj, *embproj, *boc, *cst, *gates, *q, *logits_all, *ctxdot;
    SYM(ench, g_ench); SYM(encl, g_encl);
    SYM(efh, g_efh);   SYM(efl, g_efl);
    SYM(encproj, g_encproj); SYM(embproj, g_embproj);
    SYM(wgh, g_wgh);   SYM(wgl, g_wgl);
    SYM(wdh, g_wdh);   SYM(wdl, g_wdl);
    SYM(weh, g_weh);   SYM(wel, g_wel);
    SYM(waph, g_waph); SYM(wapl, g_wapl);
    SYM(woch, g_woch); SYM(wocl, g_wocl); SYM(boc, g_boc);
    SYM(wih, g_wih);   SYM(wil, g_wil);
    SYM(hh, g_hh);     SYM(hl, g_hl);
    SYM(cst, g_c);     SYM(gates, g_gates);
    SYM(q, g_q);
    SYM(ctxh, g_ctxh); SYM(ctxl, g_ctxl);
    SYM(ahh, g_ahh_all); SYM(ahl, g_ahl_all);
    SYM(logits_all, g_logits_all); SYM(ctxdot, g_ctxdot);

    cudaFuncSetAttribute(mma_gemm_k<128, false, false>,
                         cudaFuncAttributeMaxDynamicSharedMemorySize, SM128);
    cudaFuncSetAttribute(mma_gemm_k<64, false, false>,
                         cudaFuncAttributeMaxDynamicSharedMemorySize, SM64);
    cudaFuncSetAttribute(mma_gemm_k<64, false, true>,
                         cudaFuncAttributeMaxDynamicSharedMemorySize, SM64);
    cudaFuncSetAttribute(mma_gemm_k<64, true, true>,
                         cudaFuncAttributeMaxDynamicSharedMemorySize, SM64);

    // ---- prep ----
    split_arr_k<<<4096, 256>>>(enc, ench, encl, (size_t)BATCH * SEQ * HE);
    split_arr_k<<<2048, 256>>>(enc_final, efh, efl, (size_t)BATCH * HE);
    embproj_k<<<dim3(16, VOC), 128>>>(embed, W_ih, b_ih, b_hh, embproj);
    split_arr_k<<<2048, 256>>>(W_hh, wgh, wgl, (size_t)4 * HD * HD);
    transpose_split_k<<<1024, 256>>>(W_dec_attn, wdh, wdl, HD, HD);
    transpose_split_k<<<1024, 256>>>(W_enc_attn, weh, wel, HE, HD);
    split_arr_k<<<1024, 256>>>(W_ap, waph, wapl, (size_t)HD * (HD + HE));
    prep_outw_k<<<256, 256>>>(W_out, b_out, w_copy, b_copy, woch, wocl, boc);
    split_arr_k<<<1024, 256>>>(W_init, wih, wil, (size_t)HD * HE);
    zero_c_k<<<(BATCH * HD + 255) / 256, 256>>>(cst);

    // h0 = enc_final @ W_init^T + b_init  -> splits
    mma_gemm_k<64, false, true><<<dim3(8, 32), 256, SM64>>>(
        efh, efl, HE, HE, nullptr, nullptr, 0,
        wih, wil, HE, b_init,
        nullptr, hh, hl, HE, HD);
    // enc_proj = enc @ W_enc_attn
    mma_gemm_k<128, false, false><<<dim3(4, 768), 256, SM128>>>(
        ench, encl, HE, HE, nullptr, nullptr, 0,
        weh, wel, HE, nullptr,
        encproj, nullptr, nullptr, HE, HD);

    for (int t = 0; t < TT; t++) {
        // gates_h = h @ W_hh^T   (emb part added in lstm_cell)
        mma_gemm_k<128, false, false><<<dim3(16, 32), 256, SM128>>>(
            hh, hl, HD, HD, nullptr, nullptr, 0,
            wgh, wgl, HD, nullptr,
            gates, nullptr, nullptr, HD, 4 * HD);
        lstm_cell_k<<<(BATCH * HD + 255) / 256, 256>>>(
            gates, embproj, tgt, hh, hl, cst, t);
        // q = h @ W_dec_attn + b_attn
        mma_gemm_k<64, false, false><<<dim3(8, 32), 256, SM64>>>(
            hh, hl, HD, HD, nullptr, nullptr, 0,
            wdh, wdl, HD, b_attn,
            q, nullptr, nullptr, HD, HD);
        attn_k<<<BATCH, 128>>>(encproj, enc, q, v_attn, w_copy,
                               attn_base, ctxh, ctxl, ctxdot, t);
        // ah = tanh([h | ctx] @ W_ap^T + b_ap) -> splits into per-step slice
        mma_gemm_k<64, true, true><<<dim3(8, 32), 256, SM64>>>(
            hh, hl, HD, HD,
            ctxh, ctxl, HE,
            waph, wapl, HD + HE, b_ap,
            nullptr,
            ahh + (size_t)t * BATCH * HD, ahl + (size_t)t * BATCH * HD,
            HD + HE, HD);
    }

    // deferred: logits+copy GEMM over all (t,b): M = T*B, N = 121, K = 512
    mma_gemm_k<128, false, false><<<dim3(1, (TT * BATCH) / 128), 256, SM128>>>(
        ahh, ahl, HD, HD, nullptr, nullptr, 0,
        woch, wocl, HD, boc,
        logits_all, nullptr, nullptr, HD, 121);
    out2_k<<<TT * BATCH, 128>>>(logits_all, ctxdot, input_ids, attn_base, outputs);
}